// round 16
// baseline (speedup 1.0000x reference)
#include <cuda_runtime.h>
#include <cuda_fp16.h>
#include <math.h>

#define N_NODES  100000
#define N_EDGES  3200000
#define N_GRAPHS 512
#define DIM      128
#define NLAYERS  3
#define DCAT     384
#define NCLS     10
#define BN_EPS   1e-5f

#define M_TILES  6252           // ceil(100000/16)
#define SCAN_NB  98             // ceil(100000/1024)
#define COL_CAP  (N_EDGES + 8 * N_NODES)   // padded CSR capacity

// Scratch (device globals; no allocations allowed)
__device__ __half g_hh0[(N_NODES + 1) * DIM];   // fp16 h ping (+ zero sentinel)
__device__ __half g_hh1[(N_NODES + 1) * DIM];   // fp16 h pong (+ zero sentinel)
__device__ float g_pooled[N_GRAPHS * DCAT];
__device__ float g_hfin[N_GRAPHS * DCAT];
// CSR scratch
__device__ int g_counts[N_NODES + 4];
__device__ int g_rowstart[N_NODES + 4];
__device__ int g_cursor[N_NODES + 4];
__device__ int g_col[COL_CAP];
__device__ int g_bsum[SCAN_NB + 4];
// fp16 weight fragments (m16n8k16 B layout): [l2(6)][w(16)][kt(8)][lane(32)]
#define WFRAG_PER_L2 (16 * 8 * 32)
__device__ uint2 g_wfh[6 * WFRAG_PER_L2];
__device__ uint2 g_wfl[6 * WFRAG_PER_L2];

// One merged init: counts=0, pooled=0, sentinel rows of hh0/hh1 = 0.
__global__ void init_kernel(int* __restrict__ counts, float* __restrict__ pooled,
                            __half* __restrict__ s0, __half* __restrict__ s1) {
    int i = blockIdx.x * blockDim.x + threadIdx.x;
    if (i < N_NODES + 4) counts[i] = 0;
    if (i < N_GRAPHS * DCAT) pooled[i] = 0.f;
    if (i < DIM) { s0[i] = __ushort_as_half(0); s1[i] = __ushort_as_half(0); }
}

// Convert x (fp32) -> fp16 shadow; 4 floats per thread.
__global__ void x2h_kernel(const float4* __restrict__ x, uint2* __restrict__ hh) {
    int i = blockIdx.x * blockDim.x + threadIdx.x;
    if (i >= N_NODES * DIM / 4) return;
    float4 v = __ldg(&x[i]);
    __half2 a = __float22half2_rn(make_float2(v.x, v.y));
    __half2 b = __float22half2_rn(make_float2(v.z, v.w));
    hh[i] = make_uint2(*(unsigned*)&a, *(unsigned*)&b);
}

// ---------------- CSR build (counting sort of edges by dst) ----------------
__global__ void hist_kernel(const int* __restrict__ ei, int* __restrict__ counts) {
    int i = blockIdx.x * blockDim.x + threadIdx.x;
    int e = i * 4;
    if (e + 4 <= N_EDGES) {
        int4 d = __ldg((const int4*)(ei + N_EDGES + e));
        atomicAdd(&counts[d.x], 1);
        atomicAdd(&counts[d.y], 1);
        atomicAdd(&counts[d.z], 1);
        atomicAdd(&counts[d.w], 1);
    } else {
        for (int j = e; j < N_EDGES; j++)
            atomicAdd(&counts[__ldg(&ei[N_EDGES + j])], 1);
    }
}

__global__ void __launch_bounds__(1024) scan1_kernel(
        const int* __restrict__ counts, int* __restrict__ rowstart,
        int* __restrict__ bsum) {
    __shared__ int wsum[32];
    int t = threadIdx.x;
    int i = blockIdx.x * 1024 + t;
    int c = (i < N_NODES) ? ((__ldg(&counts[i]) + 7) & ~7) : 0;
    int v = c;
#pragma unroll
    for (int off = 1; off < 32; off <<= 1) {
        int u = __shfl_up_sync(0xFFFFFFFFu, v, off);
        if ((t & 31) >= off) v += u;
    }
    if ((t & 31) == 31) wsum[t >> 5] = v;
    __syncthreads();
    if (t < 32) {
        int w = wsum[t];
#pragma unroll
        for (int off = 1; off < 32; off <<= 1) {
            int u = __shfl_up_sync(0xFFFFFFFFu, w, off);
            if (t >= off) w += u;
        }
        wsum[t] = w;
    }
    __syncthreads();
    int excl = v - c + ((t >= 32) ? wsum[(t >> 5) - 1] : 0);
    if (i < N_NODES) rowstart[i] = excl;
    if (t == 1023) bsum[blockIdx.x] = excl + c;
}

__global__ void __launch_bounds__(32) scan2_kernel(int* __restrict__ bsum) {
    int t = threadIdx.x;
    int v[4];
    int part = 0;
#pragma unroll
    for (int j = 0; j < 4; j++) {
        int idx = t * 4 + j;
        v[j] = (idx < SCAN_NB) ? bsum[idx] : 0;
        part += v[j];
    }
    int p = part;
#pragma unroll
    for (int off = 1; off < 32; off <<= 1) {
        int u = __shfl_up_sync(0xFFFFFFFFu, p, off);
        if (t >= off) p += u;
    }
    int run = p - part;
#pragma unroll
    for (int j = 0; j < 4; j++) {
        int idx = t * 4 + j;
        if (idx < SCAN_NB) bsum[idx] = run;
        run += v[j];
    }
    if (t == 31) bsum[SCAN_NB] = run;
}

// Phase 3 + pad: add block offsets, write cursor, fill pad slots w/ sentinel.
__global__ void __launch_bounds__(1024) scan3_kernel(
        const int* __restrict__ bsum, const int* __restrict__ counts,
        int* __restrict__ rowstart, int* __restrict__ cursor,
        int* __restrict__ col) {
    int i = blockIdx.x * 1024 + threadIdx.x;
    if (i < N_NODES) {
        int v = rowstart[i] + __ldg(&bsum[blockIdx.x]);
        rowstart[i] = v;
        cursor[i] = v;
        int c = __ldg(&counts[i]);
        int pc = (c + 7) & ~7;
        for (int j = c; j < pc; j++) col[v + j] = N_NODES;
    }
    if (i == 0) rowstart[N_NODES] = bsum[SCAN_NB];
}

__global__ void fill_kernel(const int* __restrict__ ei,
                            int* __restrict__ cursor, int* __restrict__ col) {
    int i = blockIdx.x * blockDim.x + threadIdx.x;
    int e = i * 4;
    if (e + 4 <= N_EDGES) {
        int4 s = __ldg((const int4*)(ei + e));
        int4 d = __ldg((const int4*)(ei + N_EDGES + e));
        col[atomicAdd(&cursor[d.x], 1)] = s.x;
        col[atomicAdd(&cursor[d.y], 1)] = s.y;
        col[atomicAdd(&cursor[d.z], 1)] = s.z;
        col[atomicAdd(&cursor[d.w], 1)] = s.w;
    } else {
        for (int j = e; j < N_EDGES; j++) {
            int s = __ldg(&ei[j]);
            int d = __ldg(&ei[N_EDGES + j]);
            col[atomicAdd(&cursor[d], 1)] = s;
        }
    }
}

// -------- Weight fragment precompute (fp16 hi/lo, m16n8k16 B layout) -------
__global__ void wfrag_kernel(const float* __restrict__ W1,
                             const float* __restrict__ W2,
                             uint2* __restrict__ wfh, uint2* __restrict__ wfl) {
    int idx = blockIdx.x * blockDim.x + threadIdx.x;
    if (idx >= 6 * WFRAG_PER_L2) return;
    int lane = idx & 31;
    int kt   = (idx >> 5) & 7;
    int w    = (idx >> 8) & 15;
    int l2   = idx >> 12;
    int g = lane >> 2, tg = lane & 3;
    int n = w * 8 + g;
    const float* Wm = (l2 & 1) ? (W2 + (l2 >> 1) * DIM * DIM)
                               : (W1 + (l2 >> 1) * DIM * DIM);
    unsigned rh[2], rl[2];
#pragma unroll
    for (int j = 0; j < 2; j++) {
        int k0 = kt * 16 + j * 8 + tg * 2;
        float v0 = __ldg(&Wm[k0 * DIM + n]);
        float v1 = __ldg(&Wm[(k0 + 1) * DIM + n]);
        __half h0 = __float2half_rn(v0);
        __half h1 = __float2half_rn(v1);
        __half l0 = __float2half_rn(v0 - __half2float(h0));
        __half l1 = __float2half_rn(v1 - __half2float(h1));
        __half2 ph = __halves2half2(h0, h1);
        __half2 pl = __halves2half2(l0, l1);
        rh[j] = *(unsigned*)&ph;
        rl[j] = *(unsigned*)&pl;
    }
    wfh[idx] = make_uint2(rh[0], rh[1]);
    wfl[idx] = make_uint2(rl[0], rl[1]);
}

// ==================== FUSED LAYER (warp-specialized) =======================
// 256 threads, occ 2.  Warps 0-3: producers (gather rows -> Ah ring, 2 stages)
// Warps 4-7: consumers (MLP1 -> Zh -> MLP2 -> hout + pooled atomics)
// Named barriers: 1+s FULL (prod arrive / cons sync), 3+s EMPTY (cons arrive /
// prod sync), 5 & 6 consumer-internal (Zh hazard).
#define MMA16816(C, A0, A1, A2, A3, B0, B1)                                   \
    asm volatile("mma.sync.aligned.m16n8k16.row.col.f32.f16.f16.f32 "         \
                 "{%0,%1,%2,%3}, {%4,%5,%6,%7}, {%8,%9}, {%0,%1,%2,%3};"      \
                 : "+f"(C[0]), "+f"(C[1]), "+f"(C[2]), "+f"(C[3])             \
                 : "r"(A0), "r"(A1), "r"(A2), "r"(A3), "r"(B0), "r"(B1))

#define LDSM4(R0, R1, R2, R3, ADDR)                                           \
    asm volatile("ldmatrix.sync.aligned.m8n8.x4.shared.b16 {%0,%1,%2,%3}, [%4];" \
                 : "=r"(R0), "=r"(R1), "=r"(R2), "=r"(R3) : "r"(ADDR))

#define BAR_SYNC(id, cnt)   asm volatile("bar.sync %0, %1;"   :: "r"(id), "r"(cnt) : "memory")
#define BAR_ARRIVE(id, cnt) asm volatile("bar.arrive %0, %1;" :: "r"(id), "r"(cnt) : "memory")

#define ZSTR 136
#define H2(u) (*(__half2*)&(u))

__device__ __forceinline__ void gather_row(
        const __half* __restrict__ hin, const int* __restrict__ rowstart,
        const int* __restrict__ col, int row, __half* __restrict__ dst,
        int l16) {
    uint4 o = make_uint4(0u, 0u, 0u, 0u);
    if (row < N_NODES) {
        float acc[8];
        int beg = __ldg(&rowstart[row]);
        int end = __ldg(&rowstart[row + 1]);
        uint4 r0 = __ldg((const uint4*)(hin + (long long)row * DIM) + l16);
        float2 f0 = __half22float2(H2(r0.x));
        float2 f1 = __half22float2(H2(r0.y));
        float2 f2 = __half22float2(H2(r0.z));
        float2 f3 = __half22float2(H2(r0.w));
        acc[0] = f0.x; acc[1] = f0.y; acc[2] = f1.x; acc[3] = f1.y;
        acc[4] = f2.x; acc[5] = f2.y; acc[6] = f3.x; acc[7] = f3.y;
        for (int i = beg; i < end; i += 8) {
            int4 c0 = __ldg((const int4*)(col + i));
            int4 c1 = __ldg((const int4*)(col + i + 4));
            uint4 r[8];
            r[0] = __ldg((const uint4*)(hin + (long long)c0.x * DIM) + l16);
            r[1] = __ldg((const uint4*)(hin + (long long)c0.y * DIM) + l16);
            r[2] = __ldg((const uint4*)(hin + (long long)c0.z * DIM) + l16);
            r[3] = __ldg((const uint4*)(hin + (long long)c0.w * DIM) + l16);
            r[4] = __ldg((const uint4*)(hin + (long long)c1.x * DIM) + l16);
            r[5] = __ldg((const uint4*)(hin + (long long)c1.y * DIM) + l16);
            r[6] = __ldg((const uint4*)(hin + (long long)c1.z * DIM) + l16);
            r[7] = __ldg((const uint4*)(hin + (long long)c1.w * DIM) + l16);
            __half2 sx = __hadd2(__hadd2(__hadd2(H2(r[0].x), H2(r[1].x)),
                                         __hadd2(H2(r[2].x), H2(r[3].x))),
                                 __hadd2(__hadd2(H2(r[4].x), H2(r[5].x)),
                                         __hadd2(H2(r[6].x), H2(r[7].x))));
            __half2 sy = __hadd2(__hadd2(__hadd2(H2(r[0].y), H2(r[1].y)),
                                         __hadd2(H2(r[2].y), H2(r[3].y))),
                                 __hadd2(__hadd2(H2(r[4].y), H2(r[5].y)),
                                         __hadd2(H2(r[6].y), H2(r[7].y))));
            __half2 sz = __hadd2(__hadd2(__hadd2(H2(r[0].z), H2(r[1].z)),
                                         __hadd2(H2(r[2].z), H2(r[3].z))),
                                 __hadd2(__hadd2(H2(r[4].z), H2(r[5].z)),
                                         __hadd2(H2(r[6].z), H2(r[7].z))));
            __half2 sw = __hadd2(__hadd2(__hadd2(H2(r[0].w), H2(r[1].w)),
                                         __hadd2(H2(r[2].w), H2(r[3].w))),
                                 __hadd2(__hadd2(H2(r[4].w), H2(r[5].w)),
                                         __hadd2(H2(r[6].w), H2(r[7].w))));
            float2 q;
            q = __half22float2(sx); acc[0] += q.x; acc[1] += q.y;
            q = __half22float2(sy); acc[2] += q.x; acc[3] += q.y;
            q = __half22float2(sz); acc[4] += q.x; acc[5] += q.y;
            q = __half22float2(sw); acc[6] += q.x; acc[7] += q.y;
        }
        __half2 p0 = __float22half2_rn(make_float2(acc[0], acc[1]));
        __half2 p1 = __float22half2_rn(make_float2(acc[2], acc[3]));
        __half2 p2 = __float22half2_rn(make_float2(acc[4], acc[5]));
        __half2 p3 = __float22half2_rn(make_float2(acc[6], acc[7]));
        o.x = *(unsigned*)&p0; o.y = *(unsigned*)&p1;
        o.z = *(unsigned*)&p2; o.w = *(unsigned*)&p3;
    }
    *(uint4*)(dst + l16 * 8) = o;
}

__global__ void __launch_bounds__(256, 2) layer_kernel(
        const __half* __restrict__ hin, __half* __restrict__ hout,
        const uint2* __restrict__ w1h, const uint2* __restrict__ w1l,
        const uint2* __restrict__ w2h, const uint2* __restrict__ w2l,
        const float* __restrict__ b1,
        const float* __restrict__ gamma, const float* __restrict__ beta,
        const float* __restrict__ rmean, const float* __restrict__ rvar,
        const float* __restrict__ b2,
        const int* __restrict__ batch, float* __restrict__ pooled, int pool_off,
        const int* __restrict__ rowstart, const int* __restrict__ col) {
    __shared__ __half Ah[2][16 * ZSTR];
    __shared__ __half Zh[16 * ZSTR];

    int tid = threadIdx.x;

    if (tid < 128) {
        // ================= PRODUCER: warps 0-3 =================
        int hw = tid >> 4;          // 0..7
        int l16 = tid & 15;
        int it = 0;
        for (int mt = blockIdx.x; mt < M_TILES; mt += gridDim.x, it++) {
            int s = it & 1;
            if (it >= 2) BAR_SYNC(3 + s, 256);        // wait empty
            gather_row(hin, rowstart, col, mt * 16 + hw,
                       &Ah[s][hw * ZSTR], l16);
            gather_row(hin, rowstart, col, mt * 16 + hw + 8,
                       &Ah[s][(hw + 8) * ZSTR], l16);
            asm volatile("membar.cta;" ::: "memory");  // STS visible pre-arrive
            BAR_ARRIVE(1 + s, 256);                    // signal full
        }
    } else {
        // ================= CONSUMER: warps 4-7 =================
        int ctid = tid - 128;
        int cwid = ctid >> 5;       // 0..3
        int lane = ctid & 31;
        int g = lane >> 2, tg = lane & 3;

        // epilogue constants for 4 groups (cols 8*(cwid*4+j) + tg*2 + {0,1})
        float sc0[4], sh0[4], sc1[4], sh1[4], bb0[4], bb1[4];
        int col0[4];
#pragma unroll
        for (int j = 0; j < 4; j++) {
            int c = (cwid * 4 + j) * 8 + tg * 2;
            col0[j] = c;
            sc0[j] = __ldg(&gamma[c]) * rsqrtf(__ldg(&rvar[c]) + BN_EPS);
            sh0[j] = __ldg(&beta[c]) - __ldg(&rmean[c]) * sc0[j]
                     + sc0[j] * __ldg(&b1[c]);
            sc1[j] = __ldg(&gamma[c + 1]) * rsqrtf(__ldg(&rvar[c + 1]) + BN_EPS);
            sh1[j] = __ldg(&beta[c + 1]) - __ldg(&rmean[c + 1]) * sc1[j]
                     + sc1[j] * __ldg(&b1[c + 1]);
            bb0[j] = __ldg(&b2[c]);
            bb1[j] = __ldg(&b2[c + 1]);
        }
        // W-frag base pointers per group
        const uint2 *p1h[4], *p1l[4], *p2h[4], *p2l[4];
#pragma unroll
        for (int j = 0; j < 4; j++) {
            int w = cwid * 4 + j;
            p1h[j] = w1h + w * 256 + lane;
            p1l[j] = w1l + w * 256 + lane;
            p2h[j] = w2h + w * 256 + lane;
            p2l[j] = w2l + w * 256 + lane;
        }

        unsigned baseA0, baseA1, baseZ;
        {
            unsigned off = (lane & 15) * (ZSTR * 2) + (lane >> 4) * 16;
            baseA0 = (unsigned)__cvta_generic_to_shared(&Ah[0][0]) + off;
            baseA1 = (unsigned)__cvta_generic_to_shared(&Ah[1][0]) + off;
            baseZ  = (unsigned)__cvta_generic_to_shared(&Zh[0]) + off;
        }

        int it = 0;
        for (int mt = blockIdx.x; mt < M_TILES; mt += gridDim.x, it++) {
            int s = it & 1;
            BAR_SYNC(1 + s, 256);                      // wait full
            unsigned bah = s ? baseA1 : baseA0;

            float c[4][4], e[4][4];
#pragma unroll
            for (int j = 0; j < 4; j++)
#pragma unroll
                for (int q = 0; q < 4; q++) { c[j][q] = 0.f; e[j][q] = 0.f; }

            // ---- MLP1 ----
#pragma unroll
            for (int kt = 0; kt < 8; kt++) {
                unsigned x0, x1, x2, x3;
                LDSM4(x0, x1, x2, x3, bah + kt * 32);
#pragma unroll
                for (int j = 0; j < 4; j++) {
                    uint2 wh = __ldg(p1h[j] + kt * 32);
                    uint2 wl = __ldg(p1l[j] + kt * 32);
                    MMA16816(c[j], x0, x1, x2, x3, wh.x, wh.y);
                    MMA16816(e[j], x0, x1, x2, x3, wl.x, wl.y);
                }
            }
            BAR_ARRIVE(3 + s, 256);                    // Ah[s] consumed
#pragma unroll
            for (int j = 0; j < 4; j++) {
                float y00 = fmaxf(sc0[j] * (c[j][0] + e[j][0]) + sh0[j], 0.f);
                float y01 = fmaxf(sc1[j] * (c[j][1] + e[j][1]) + sh1[j], 0.f);
                float y10 = fmaxf(sc0[j] * (c[j][2] + e[j][2]) + sh0[j], 0.f);
                float y11 = fmaxf(sc1[j] * (c[j][3] + e[j][3]) + sh1[j], 0.f);
                *(__half2*)&Zh[g * ZSTR + col0[j]] =
                    __float22half2_rn(make_float2(y00, y01));
                *(__half2*)&Zh[(g + 8) * ZSTR + col0[j]] =
                    __float22half2_rn(make_float2(y10, y11));
            }
            BAR_SYNC(5, 128);                          // Zh visible

            // ---- MLP2 ----
#pragma unroll
            for (int j = 0; j < 4; j++)
#pragma unroll
                for (int q = 0; q < 4; q++) { c[j][q] = 0.f; e[j][q] = 0.f; }
#pragma unroll
            for (int kt = 0; kt < 8; kt++) {
                unsigned x0, x1, x2, x3;
                LDSM4(x0, x1, x2, x3, baseZ + kt * 32);
#pragma unroll
                for (int j = 0; j < 4; j++) {
                    uint2 wh = __ldg(p2h[j] + kt * 32);
                    uint2 wl = __ldg(p2l[j] + kt * 32);
                    MMA16816(c[j], x0, x1, x2, x3, wh.x, wh.y);
                    MMA16816(e[j], x0, x1, x2, x3, wl.x, wl.y);
                }
            }
            BAR_SYNC(6, 128);                          // Zh reads done

            int r0 = mt * 16 + g;
            int r1 = r0 + 8;
            if (r0 < N_NODES) {
                int bi = __ldg(&batch[r0]);
                float* pb = pooled + bi * DCAT + pool_off;
#pragma unroll
                for (int j = 0; j < 4; j++) {
                    float y0 = fmaxf(c[j][0] + e[j][0] + bb0[j], 0.f);
                    float y1 = fmaxf(c[j][1] + e[j][1] + bb1[j], 0.f);
                    *(__half2*)(hout + (long long)r0 * DIM + col0[j]) =
                        __float22half2_rn(make_float2(y0, y1));
                    asm volatile("red.global.add.v2.f32 [%0], {%1,%2};"
                                 :: "l"(pb + col0[j]), "f"(y0), "f"(y1) : "memory");
                }
            }
            if (r1 < N_NODES) {
                int bi = __ldg(&batch[r1]);
                float* pb = pooled + bi * DCAT + pool_off;
#pragma unroll
                for (int j = 0; j < 4; j++) {
                    float y0 = fmaxf(c[j][2] + e[j][2] + bb0[j], 0.f);
                    float y1 = fmaxf(c[j][3] + e[j][3] + bb1[j], 0.f);
                    *(__half2*)(hout + (long long)r1 * DIM + col0[j]) =
                        __float22half2_rn(make_float2(y0, y1));
                    asm volatile("red.global.add.v2.f32 [%0], {%1,%2};"
                                 :: "l"(pb + col0[j]), "f"(y0), "f"(y1) : "memory");
                }
            }
        }
    }
}

// h_fin = relu(pooled @ Wfin + bfin)
__global__ void __launch_bounds__(DCAT) fin1_kernel(
        const float* __restrict__ pooled, const float* __restrict__ Wfin,
        const float* __restrict__ bfin, float* __restrict__ hfin) {
    __shared__ float s[DCAT];
    int g = blockIdx.x;
    int j = threadIdx.x;
    s[j] = pooled[g * DCAT + j];
    __syncthreads();
    float acc0 = 0.f, acc1 = 0.f, acc2 = 0.f, acc3 = 0.f;
#pragma unroll 4
    for (int k = 0; k < DCAT; k += 4) {
        acc0 += s[k + 0] * __ldg(&Wfin[(k + 0) * DCAT + j]);
        acc1 += s[k + 1] * __ldg(&Wfin[(k + 1) * DCAT + j]);
        acc2 += s[k + 2] * __ldg(&Wfin[(k + 2) * DCAT + j]);
        acc3 += s[k + 3] * __ldg(&Wfin[(k + 3) * DCAT + j]);
    }
    float acc = (acc0 + acc1) + (acc2 + acc3) + __ldg(&bfin[j]);
    hfin[g * DCAT + j] = fmaxf(acc, 0.f);
}

// logits + log_softmax: one warp per graph.
__global__ void __launch_bounds__(32) fin2_kernel(
        const float* __restrict__ hfin, const float* __restrict__ Wout,
        const float* __restrict__ bout, float* __restrict__ out, int out_size) {
    int g = blockIdx.x;
    int lane = threadIdx.x;
    bool valid = lane < NCLS;
    float acc = valid ? __ldg(&bout[lane]) : 0.f;
    for (int k = 0; k < DCAT; k++) {
        float v = __ldg(&hfin[g * DCAT + k]);
        if (valid) acc += v * __ldg(&Wout[k * NCLS + lane]);
    }
    float logit = acc;
    float m = valid ? logit : -INFINITY;
#pragma unroll
    for (int off = 16; off > 0; off >>= 1)
        m = fmaxf(m, __shfl_xor_sync(0xFFFFFFFFu, m, off));
    float e = valid ? expf(logit - m) : 0.f;
#pragma unroll
    for (int off = 16; off > 0; off >>= 1)
        e += __shfl_xor_sync(0xFFFFFFFFu, e, off);
    float ls = logit - m - logf(e);
    if (valid) {
        out[g * NCLS + lane] = logit;
        if (out_size >= 2 * N_GRAPHS * NCLS)
            out[N_GRAPHS * NCLS + g * NCLS + lane] = ls;
    }
}

extern "C" void kernel_launch(void* const* d_in, const int* in_sizes, int n_in,
                              void* d_out, int out_size) {
    const float* x        = (const float*)d_in[0];
    const int*   ei       = (const int*)d_in[1];
    const int*   batch    = (const int*)d_in[2];

    int w = 3;
    if (n_in >= 4 && in_sizes[3] == 1) w = 4;

    const float* W1   = (const float*)d_in[w + 0];
    const float* b1   = (const float*)d_in[w + 1];
    const float* gamma= (const float*)d_in[w + 2];
    const float* beta = (const float*)d_in[w + 3];
    const float* rmean= (const float*)d_in[w + 4];
    const float* rvar = (const float*)d_in[w + 5];
    const float* W2   = (const float*)d_in[w + 6];
    const float* b2   = (const float*)d_in[w + 7];
    const float* Wfin = (const float*)d_in[w + 8];
    const float* bfin = (const float*)d_in[w + 9];
    const float* Wout = (const float*)d_in[w + 10];
    const float* bout = (const float*)d_in[w + 11];
    float* out = (float*)d_out;

    float *pooled, *hfin;
    __half *hh0, *hh1;
    uint2 *wfh, *wfl;
    int *counts, *rowstart, *cursor, *colbuf, *bsum;
    cudaGetSymbolAddress((void**)&hh0,      g_hh0);
    cudaGetSymbolAddress((void**)&hh1,      g_hh1);
    cudaGetSymbolAddress((void**)&pooled,   g_pooled);
    cudaGetSymbolAddress((void**)&hfin,     g_hfin);
    cudaGetSymbolAddress((void**)&counts,   g_counts);
    cudaGetSymbolAddress((void**)&rowstart, g_rowstart);
    cudaGetSymbolAddress((void**)&cursor,   g_cursor);
    cudaGetSymbolAddress((void**)&colbuf,   g_col);
    cudaGetSymbolAddress((void**)&bsum,     g_bsum);
    cudaGetSymbolAddress((void**)&wfh,      g_wfh);
    cudaGetSymbolAddress((void**)&wfl,      g_wfl);

    const int E4B = (N_EDGES / 4 + 255) / 256;
    const int LB = 296;   // 148 SMs x occ 2

    init_kernel<<<(N_GRAPHS * DCAT + 255) / 256 > (N_NODES + 4 + 255) / 256
                      ? (N_GRAPHS * DCAT + 255) / 256
                      : (N_NODES + 4 + 255) / 256,
                  256>>>(counts, pooled, hh0 + (long long)N_NODES * DIM,
                         hh1 + (long long)N_NODES * DIM);
    x2h_kernel<<<(N_NODES * DIM / 4 + 255) / 256, 256>>>(
        (const float4*)x, (uint2*)hh0);
    hist_kernel<<<E4B, 256>>>(ei, counts);
    scan1_kernel<<<SCAN_NB, 1024>>>(counts, rowstart, bsum);
    scan2_kernel<<<1, 32>>>(bsum);
    scan3_kernel<<<SCAN_NB, 1024>>>(bsum, counts, rowstart, cursor, colbuf);
    fill_kernel<<<E4B, 256>>>(ei, cursor, colbuf);
    wfrag_kernel<<<(6 * WFRAG_PER_L2 + 255) / 256, 256>>>(W1, W2, wfh, wfl);

    const __half* hin = hh0;
    __half* hout = hh1;
    for (int i = 0; i < NLAYERS; i++) {
        int l2a = i * 2, l2b = i * 2 + 1;
        layer_kernel<<<LB, 256>>>(
            hin, hout,
            wfh + l2a * WFRAG_PER_L2, wfl + l2a * WFRAG_PER_L2,
            wfh + l2b * WFRAG_PER_L2, wfl + l2b * WFRAG_PER_L2,
            b1 + i * DIM,
            gamma + i * DIM, beta + i * DIM, rmean + i * DIM, rvar + i * DIM,
            b2 + i * DIM,
            batch, pooled, i * DIM, rowstart, colbuf);
        const __half* t = hin;
        hin = hout;
        hout = (__half*)t;
    }

    fin1_kernel<<<N_GRAPHS, DCAT>>>(pooled, Wfin, bfin, hfin);
    fin2_kernel<<<N_GRAPHS, 32>>>(hfin, Wout, bout, out, out_size);
}

// round 17
// speedup vs baseline: 1.2640x; 1.2640x over previous
#include <cuda_runtime.h>
#include <cuda_fp16.h>
#include <math.h>

#define N_NODES  100000
#define N_EDGES  3200000
#define N_GRAPHS 512
#define DIM      128
#define NLAYERS  3
#define DCAT     384
#define NCLS     10
#define BN_EPS   1e-5f

#define M_TILES  6252           // ceil(100000/16)
#define SCAN_NB  98             // ceil(100000/1024)
#define COL_CAP  (N_EDGES + 8 * N_NODES)   // padded CSR capacity

// Scratch (device globals; no allocations allowed)
__device__ __half g_hh0[(N_NODES + 1) * DIM];   // fp16 h ping (+ zero sentinel)
__device__ __half g_hh1[(N_NODES + 1) * DIM];   // fp16 h pong (+ zero sentinel)
__device__ float g_pooled[N_GRAPHS * DCAT];
__device__ float g_hfin[N_GRAPHS * DCAT];
// CSR scratch
__device__ int g_counts[N_NODES + 4];
__device__ int g_rowstart[N_NODES + 4];
__device__ int g_cursor[N_NODES + 4];
__device__ int g_col[COL_CAP];
__device__ int g_bsum[SCAN_NB + 4];
// fp16 weight fragments (m16n8k16 B layout): [l2(6)][w(16)][kt(8)][lane(32)]
#define WFRAG_PER_L2 (16 * 8 * 32)
__device__ uint2 g_wfh[6 * WFRAG_PER_L2];
__device__ uint2 g_wfl[6 * WFRAG_PER_L2];

// One merged init: counts=0, pooled=0, sentinel rows of hh0/hh1 = 0.
__global__ void init_kernel(int* __restrict__ counts, float* __restrict__ pooled,
                            __half* __restrict__ s0, __half* __restrict__ s1) {
    int i = blockIdx.x * blockDim.x + threadIdx.x;
    if (i < N_NODES + 4) counts[i] = 0;
    if (i < N_GRAPHS * DCAT) pooled[i] = 0.f;
    if (i < DIM) { s0[i] = __ushort_as_half(0); s1[i] = __ushort_as_half(0); }
}

// Convert x (fp32) -> fp16 shadow; 4 floats per thread.
__global__ void x2h_kernel(const float4* __restrict__ x, uint2* __restrict__ hh) {
    int i = blockIdx.x * blockDim.x + threadIdx.x;
    if (i >= N_NODES * DIM / 4) return;
    float4 v = __ldg(&x[i]);
    __half2 a = __float22half2_rn(make_float2(v.x, v.y));
    __half2 b = __float22half2_rn(make_float2(v.z, v.w));
    hh[i] = make_uint2(*(unsigned*)&a, *(unsigned*)&b);
}

// ---------------- CSR build (counting sort of edges by dst) ----------------
__global__ void hist_kernel(const int* __restrict__ ei, int* __restrict__ counts) {
    int i = blockIdx.x * blockDim.x + threadIdx.x;
    int e = i * 4;
    if (e + 4 <= N_EDGES) {
        int4 d = __ldg((const int4*)(ei + N_EDGES + e));
        atomicAdd(&counts[d.x], 1);
        atomicAdd(&counts[d.y], 1);
        atomicAdd(&counts[d.z], 1);
        atomicAdd(&counts[d.w], 1);
    } else {
        for (int j = e; j < N_EDGES; j++)
            atomicAdd(&counts[__ldg(&ei[N_EDGES + j])], 1);
    }
}

__global__ void __launch_bounds__(1024) scan1_kernel(
        const int* __restrict__ counts, int* __restrict__ rowstart,
        int* __restrict__ bsum) {
    __shared__ int wsum[32];
    int t = threadIdx.x;
    int i = blockIdx.x * 1024 + t;
    int c = (i < N_NODES) ? ((__ldg(&counts[i]) + 7) & ~7) : 0;
    int v = c;
#pragma unroll
    for (int off = 1; off < 32; off <<= 1) {
        int u = __shfl_up_sync(0xFFFFFFFFu, v, off);
        if ((t & 31) >= off) v += u;
    }
    if ((t & 31) == 31) wsum[t >> 5] = v;
    __syncthreads();
    if (t < 32) {
        int w = wsum[t];
#pragma unroll
        for (int off = 1; off < 32; off <<= 1) {
            int u = __shfl_up_sync(0xFFFFFFFFu, w, off);
            if (t >= off) w += u;
        }
        wsum[t] = w;
    }
    __syncthreads();
    int excl = v - c + ((t >= 32) ? wsum[(t >> 5) - 1] : 0);
    if (i < N_NODES) rowstart[i] = excl;
    if (t == 1023) bsum[blockIdx.x] = excl + c;
}

__global__ void __launch_bounds__(32) scan2_kernel(int* __restrict__ bsum) {
    int t = threadIdx.x;
    int v[4];
    int part = 0;
#pragma unroll
    for (int j = 0; j < 4; j++) {
        int idx = t * 4 + j;
        v[j] = (idx < SCAN_NB) ? bsum[idx] : 0;
        part += v[j];
    }
    int p = part;
#pragma unroll
    for (int off = 1; off < 32; off <<= 1) {
        int u = __shfl_up_sync(0xFFFFFFFFu, p, off);
        if (t >= off) p += u;
    }
    int run = p - part;
#pragma unroll
    for (int j = 0; j < 4; j++) {
        int idx = t * 4 + j;
        if (idx < SCAN_NB) bsum[idx] = run;
        run += v[j];
    }
    if (t == 31) bsum[SCAN_NB] = run;
}

// Phase 3 + pad: add block offsets, write cursor, fill pad slots w/ sentinel.
__global__ void __launch_bounds__(1024) scan3_kernel(
        const int* __restrict__ bsum, const int* __restrict__ counts,
        int* __restrict__ rowstart, int* __restrict__ cursor,
        int* __restrict__ col) {
    int i = blockIdx.x * 1024 + threadIdx.x;
    if (i < N_NODES) {
        int v = rowstart[i] + __ldg(&bsum[blockIdx.x]);
        rowstart[i] = v;
        cursor[i] = v;
        int c = __ldg(&counts[i]);
        int pc = (c + 7) & ~7;
        for (int j = c; j < pc; j++) col[v + j] = N_NODES;
    }
    if (i == 0) rowstart[N_NODES] = bsum[SCAN_NB];
}

__global__ void fill_kernel(const int* __restrict__ ei,
                            int* __restrict__ cursor, int* __restrict__ col) {
    int i = blockIdx.x * blockDim.x + threadIdx.x;
    int e = i * 4;
    if (e + 4 <= N_EDGES) {
        int4 s = __ldg((const int4*)(ei + e));
        int4 d = __ldg((const int4*)(ei + N_EDGES + e));
        col[atomicAdd(&cursor[d.x], 1)] = s.x;
        col[atomicAdd(&cursor[d.y], 1)] = s.y;
        col[atomicAdd(&cursor[d.z], 1)] = s.z;
        col[atomicAdd(&cursor[d.w], 1)] = s.w;
    } else {
        for (int j = e; j < N_EDGES; j++) {
            int s = __ldg(&ei[j]);
            int d = __ldg(&ei[N_EDGES + j]);
            col[atomicAdd(&cursor[d], 1)] = s;
        }
    }
}

// -------- Weight fragment precompute (fp16 hi/lo, m16n8k16 B layout) -------
__global__ void wfrag_kernel(const float* __restrict__ W1,
                             const float* __restrict__ W2,
                             uint2* __restrict__ wfh, uint2* __restrict__ wfl) {
    int idx = blockIdx.x * blockDim.x + threadIdx.x;
    if (idx >= 6 * WFRAG_PER_L2) return;
    int lane = idx & 31;
    int kt   = (idx >> 5) & 7;
    int w    = (idx >> 8) & 15;
    int l2   = idx >> 12;
    int g = lane >> 2, tg = lane & 3;
    int n = w * 8 + g;
    const float* Wm = (l2 & 1) ? (W2 + (l2 >> 1) * DIM * DIM)
                               : (W1 + (l2 >> 1) * DIM * DIM);
    unsigned rh[2], rl[2];
#pragma unroll
    for (int j = 0; j < 2; j++) {
        int k0 = kt * 16 + j * 8 + tg * 2;
        float v0 = __ldg(&Wm[k0 * DIM + n]);
        float v1 = __ldg(&Wm[(k0 + 1) * DIM + n]);
        __half h0 = __float2half_rn(v0);
        __half h1 = __float2half_rn(v1);
        __half l0 = __float2half_rn(v0 - __half2float(h0));
        __half l1 = __float2half_rn(v1 - __half2float(h1));
        __half2 ph = __halves2half2(h0, h1);
        __half2 pl = __halves2half2(l0, l1);
        rh[j] = *(unsigned*)&ph;
        rl[j] = *(unsigned*)&pl;
    }
    wfh[idx] = make_uint2(rh[0], rh[1]);
    wfl[idx] = make_uint2(rl[0], rl[1]);
}

// ==================== FUSED LAYER: gather + MLP1 + MLP2 ====================
// (R14 uniform-warp structure — measured best.)
// 256 threads, occupancy 2. Grid-stride over 16-row tiles.
#define MMA16816(C, A0, A1, A2, A3, B0, B1)                                   \
    asm volatile("mma.sync.aligned.m16n8k16.row.col.f32.f16.f16.f32 "         \
                 "{%0,%1,%2,%3}, {%4,%5,%6,%7}, {%8,%9}, {%0,%1,%2,%3};"      \
                 : "+f"(C[0]), "+f"(C[1]), "+f"(C[2]), "+f"(C[3])             \
                 : "r"(A0), "r"(A1), "r"(A2), "r"(A3), "r"(B0), "r"(B1))

#define LDSM4(R0, R1, R2, R3, ADDR)                                           \
    asm volatile("ldmatrix.sync.aligned.m8n8.x4.shared.b16 {%0,%1,%2,%3}, [%4];" \
                 : "=r"(R0), "=r"(R1), "=r"(R2), "=r"(R3) : "r"(ADDR))

#define ZSTR 136
#define H2(u) (*(__half2*)&(u))

__global__ void __launch_bounds__(256, 2) layer_kernel(
        const __half* __restrict__ hin, __half* __restrict__ hout,
        const uint2* __restrict__ w1h, const uint2* __restrict__ w1l,
        const uint2* __restrict__ w2h, const uint2* __restrict__ w2l,
        const float* __restrict__ b1,
        const float* __restrict__ gamma, const float* __restrict__ beta,
        const float* __restrict__ rmean, const float* __restrict__ rvar,
        const float* __restrict__ b2,
        const int* __restrict__ batch, float* __restrict__ pooled, int pool_off,
        const int* __restrict__ rowstart, const int* __restrict__ col) {
    __shared__ __half Ah[16 * ZSTR];
    __shared__ __half Zh[16 * ZSTR];

    int tid = threadIdx.x;
    int wid = tid >> 5;          // 0..7
    int lane = tid & 31;
    int g = lane >> 2, tg = lane & 3;
    int hw = tid >> 4;           // 0..15 half-warp = tile row
    int l16 = tid & 15;

    // epilogue constants for the 4 cols this thread owns
    int colA = wid * 16 + tg * 2;
    int colB = colA + 8;
    float scA0 = __ldg(&gamma[colA]) * rsqrtf(__ldg(&rvar[colA]) + BN_EPS);
    float shA0 = __ldg(&beta[colA]) - __ldg(&rmean[colA]) * scA0
                 + scA0 * __ldg(&b1[colA]);
    float scA1 = __ldg(&gamma[colA + 1]) * rsqrtf(__ldg(&rvar[colA + 1]) + BN_EPS);
    float shA1 = __ldg(&beta[colA + 1]) - __ldg(&rmean[colA + 1]) * scA1
                 + scA1 * __ldg(&b1[colA + 1]);
    float scB0 = __ldg(&gamma[colB]) * rsqrtf(__ldg(&rvar[colB]) + BN_EPS);
    float shB0 = __ldg(&beta[colB]) - __ldg(&rmean[colB]) * scB0
                 + scB0 * __ldg(&b1[colB]);
    float scB1 = __ldg(&gamma[colB + 1]) * rsqrtf(__ldg(&rvar[colB + 1]) + BN_EPS);
    float shB1 = __ldg(&beta[colB + 1]) - __ldg(&rmean[colB + 1]) * scB1
                 + scB1 * __ldg(&b1[colB + 1]);
    float bbA0 = __ldg(&b2[colA]), bbA1 = __ldg(&b2[colA + 1]);
    float bbB0 = __ldg(&b2[colB]), bbB1 = __ldg(&b2[colB + 1]);

    // W-frag pointers: layout index = (w*8 + kt)*32 + lane
    const uint2* w1hA = w1h + (wid * 2) * 8 * 32 + lane;
    const uint2* w1lA = w1l + (wid * 2) * 8 * 32 + lane;
    const uint2* w1hB = w1h + (wid * 2 + 1) * 8 * 32 + lane;
    const uint2* w1lB = w1l + (wid * 2 + 1) * 8 * 32 + lane;
    const uint2* w2hA = w2h + (wid * 2) * 8 * 32 + lane;
    const uint2* w2lA = w2l + (wid * 2) * 8 * 32 + lane;
    const uint2* w2hB = w2h + (wid * 2 + 1) * 8 * 32 + lane;
    const uint2* w2lB = w2l + (wid * 2 + 1) * 8 * 32 + lane;

    unsigned baseA, baseZ;
    {
        unsigned off = (lane & 15) * (ZSTR * 2) + (lane >> 4) * 16;
        baseA = (unsigned)__cvta_generic_to_shared(&Ah[0]) + off;
        baseZ = (unsigned)__cvta_generic_to_shared(&Zh[0]) + off;
    }

    for (int mt = blockIdx.x; mt < M_TILES; mt += gridDim.x) {
        // ---------- gather: row (mt*16+hw) -> Ah[hw] (fp16) ----------
        {
            int row = mt * 16 + hw;
            float acc[8] = {0.f, 0.f, 0.f, 0.f, 0.f, 0.f, 0.f, 0.f};
            if (row < N_NODES) {
                int beg = __ldg(&rowstart[row]);
                int end = __ldg(&rowstart[row + 1]);
                uint4 r0 = __ldg((const uint4*)(hin + (long long)row * DIM) + l16);
                float2 f0 = __half22float2(H2(r0.x));
                float2 f1 = __half22float2(H2(r0.y));
                float2 f2 = __half22float2(H2(r0.z));
                float2 f3 = __half22float2(H2(r0.w));
                acc[0] = f0.x; acc[1] = f0.y; acc[2] = f1.x; acc[3] = f1.y;
                acc[4] = f2.x; acc[5] = f2.y; acc[6] = f3.x; acc[7] = f3.y;
                for (int i = beg; i < end; i += 8) {
                    int4 c0 = __ldg((const int4*)(col + i));
                    int4 c1 = __ldg((const int4*)(col + i + 4));
                    uint4 r[8];
                    r[0] = __ldg((const uint4*)(hin + (long long)c0.x * DIM) + l16);
                    r[1] = __ldg((const uint4*)(hin + (long long)c0.y * DIM) + l16);
                    r[2] = __ldg((const uint4*)(hin + (long long)c0.z * DIM) + l16);
                    r[3] = __ldg((const uint4*)(hin + (long long)c0.w * DIM) + l16);
                    r[4] = __ldg((const uint4*)(hin + (long long)c1.x * DIM) + l16);
                    r[5] = __ldg((const uint4*)(hin + (long long)c1.y * DIM) + l16);
                    r[6] = __ldg((const uint4*)(hin + (long long)c1.z * DIM) + l16);
                    r[7] = __ldg((const uint4*)(hin + (long long)c1.w * DIM) + l16);
                    __half2 sx = __hadd2(
                        __hadd2(__hadd2(H2(r[0].x), H2(r[1].x)),
                                __hadd2(H2(r[2].x), H2(r[3].x))),
                        __hadd2(__hadd2(H2(r[4].x), H2(r[5].x)),
                                __hadd2(H2(r[6].x), H2(r[7].x))));
                    __half2 sy = __hadd2(
                        __hadd2(__hadd2(H2(r[0].y), H2(r[1].y)),
                                __hadd2(H2(r[2].y), H2(r[3].y))),
                        __hadd2(__hadd2(H2(r[4].y), H2(r[5].y)),
                                __hadd2(H2(r[6].y), H2(r[7].y))));
                    __half2 sz = __hadd2(
                        __hadd2(__hadd2(H2(r[0].z), H2(r[1].z)),
                                __hadd2(H2(r[2].z), H2(r[3].z))),
                        __hadd2(__hadd2(H2(r[4].z), H2(r[5].z)),
                                __hadd2(H2(r[6].z), H2(r[7].z))));
                    __half2 sw = __hadd2(
                        __hadd2(__hadd2(H2(r[0].w), H2(r[1].w)),
                                __hadd2(H2(r[2].w), H2(r[3].w))),
                        __hadd2(__hadd2(H2(r[4].w), H2(r[5].w)),
                                __hadd2(H2(r[6].w), H2(r[7].w))));
                    float2 q;
                    q = __half22float2(sx); acc[0] += q.x; acc[1] += q.y;
                    q = __half22float2(sy); acc[2] += q.x; acc[3] += q.y;
                    q = __half22float2(sz); acc[4] += q.x; acc[5] += q.y;
                    q = __half22float2(sw); acc[6] += q.x; acc[7] += q.y;
                }
            }
            __half2 p0 = __float22half2_rn(make_float2(acc[0], acc[1]));
            __half2 p1 = __float22half2_rn(make_float2(acc[2], acc[3]));
            __half2 p2 = __float22half2_rn(make_float2(acc[4], acc[5]));
            __half2 p3 = __float22half2_rn(make_float2(acc[6], acc[7]));
            uint4 o;
            o.x = *(unsigned*)&p0; o.y = *(unsigned*)&p1;
            o.z = *(unsigned*)&p2; o.w = *(unsigned*)&p3;
            *(uint4*)&Ah[hw * ZSTR + l16 * 8] = o;
        }
        __syncthreads();

        // ---------- MLP1: z = ReLU(BN(aggr @ W1 + b1)) -> Zh ----------
        float cA[4] = {0.f, 0.f, 0.f, 0.f}, eA[4] = {0.f, 0.f, 0.f, 0.f};
        float cB[4] = {0.f, 0.f, 0.f, 0.f}, eB[4] = {0.f, 0.f, 0.f, 0.f};
#pragma unroll
        for (int kt = 0; kt < 8; kt++) {
            unsigned x0, x1, x2, x3;
            LDSM4(x0, x1, x2, x3, baseA + kt * 32);
            uint2 whA = __ldg(w1hA + kt * 32);
            uint2 wlA = __ldg(w1lA + kt * 32);
            uint2 whB = __ldg(w1hB + kt * 32);
            uint2 wlB = __ldg(w1lB + kt * 32);
            MMA16816(cA, x0, x1, x2, x3, whA.x, whA.y);
            MMA16816(eA, x0, x1, x2, x3, wlA.x, wlA.y);
            MMA16816(cB, x0, x1, x2, x3, whB.x, whB.y);
            MMA16816(eB, x0, x1, x2, x3, wlB.x, wlB.y);
        }
        {
            float yA00 = fmaxf(scA0 * (cA[0] + eA[0]) + shA0, 0.f);
            float yA01 = fmaxf(scA1 * (cA[1] + eA[1]) + shA1, 0.f);
            float yA10 = fmaxf(scA0 * (cA[2] + eA[2]) + shA0, 0.f);
            float yA11 = fmaxf(scA1 * (cA[3] + eA[3]) + shA1, 0.f);
            float yB00 = fmaxf(scB0 * (cB[0] + eB[0]) + shB0, 0.f);
            float yB01 = fmaxf(scB1 * (cB[1] + eB[1]) + shB1, 0.f);
            float yB10 = fmaxf(scB0 * (cB[2] + eB[2]) + shB0, 0.f);
            float yB11 = fmaxf(scB1 * (cB[3] + eB[3]) + shB1, 0.f);
            *(__half2*)&Zh[g * ZSTR + colA] =
                __float22half2_rn(make_float2(yA00, yA01));
            *(__half2*)&Zh[(g + 8) * ZSTR + colA] =
                __float22half2_rn(make_float2(yA10, yA11));
            *(__half2*)&Zh[g * ZSTR + colB] =
                __float22half2_rn(make_float2(yB00, yB01));
            *(__half2*)&Zh[(g + 8) * ZSTR + colB] =
                __float22half2_rn(make_float2(yB10, yB11));
        }
        __syncthreads();

        // ---------- MLP2: h = ReLU(z @ W2 + b2) -> hout + pool ----------
#pragma unroll
        for (int j = 0; j < 4; j++) { cA[j] = 0.f; eA[j] = 0.f; cB[j] = 0.f; eB[j] = 0.f; }
#pragma unroll
        for (int kt = 0; kt < 8; kt++) {
            unsigned x0, x1, x2, x3;
            LDSM4(x0, x1, x2, x3, baseZ + kt * 32);
            uint2 whA = __ldg(w2hA + kt * 32);
            uint2 wlA = __ldg(w2lA + kt * 32);
            uint2 whB = __ldg(w2hB + kt * 32);
            uint2 wlB = __ldg(w2lB + kt * 32);
            MMA16816(cA, x0, x1, x2, x3, whA.x, whA.y);
            MMA16816(eA, x0, x1, x2, x3, wlA.x, wlA.y);
            MMA16816(cB, x0, x1, x2, x3, whB.x, whB.y);
            MMA16816(eB, x0, x1, x2, x3, wlB.x, wlB.y);
        }
        {
            float yA00 = fmaxf(cA[0] + eA[0] + bbA0, 0.f);
            float yA01 = fmaxf(cA[1] + eA[1] + bbA1, 0.f);
            float yA10 = fmaxf(cA[2] + eA[2] + bbA0, 0.f);
            float yA11 = fmaxf(cA[3] + eA[3] + bbA1, 0.f);
            float yB00 = fmaxf(cB[0] + eB[0] + bbB0, 0.f);
            float yB01 = fmaxf(cB[1] + eB[1] + bbB1, 0.f);
            float yB10 = fmaxf(cB[2] + eB[2] + bbB0, 0.f);
            float yB11 = fmaxf(cB[3] + eB[3] + bbB1, 0.f);
            int r0 = mt * 16 + g;
            int r1 = r0 + 8;
            if (r0 < N_NODES) {
                *(__half2*)(hout + (long long)r0 * DIM + colA) =
                    __float22half2_rn(make_float2(yA00, yA01));
                *(__half2*)(hout + (long long)r0 * DIM + colB) =
                    __float22half2_rn(make_float2(yB00, yB01));
                int bi = __ldg(&batch[r0]);
                float* pb = pooled + bi * DCAT + pool_off;
                asm volatile("red.global.add.v2.f32 [%0], {%1,%2};"
                             :: "l"(pb + colA), "f"(yA00), "f"(yA01) : "memory");
                asm volatile("red.global.add.v2.f32 [%0], {%1,%2};"
                             :: "l"(pb + colB), "f"(yB00), "f"(yB01) : "memory");
            }
            if (r1 < N_NODES) {
                *(__half2*)(hout + (long long)r1 * DIM + colA) =
                    __float22half2_rn(make_float2(yA10, yA11));
                *(__half2*)(hout + (long long)r1 * DIM + colB) =
                    __float22half2_rn(make_float2(yB10, yB11));
                int bi = __ldg(&batch[r1]);
                float* pb = pooled + bi * DCAT + pool_off;
                asm volatile("red.global.add.v2.f32 [%0], {%1,%2};"
                             :: "l"(pb + colA), "f"(yA10), "f"(yA11) : "memory");
                asm volatile("red.global.add.v2.f32 [%0], {%1,%2};"
                             :: "l"(pb + colB), "f"(yB10), "f"(yB11) : "memory");
            }
        }
        __syncthreads();   // Ah/Zh reuse next tile
    }
}

// h_fin = relu(pooled @ Wfin + bfin)
__global__ void __launch_bounds__(DCAT) fin1_kernel(
        const float* __restrict__ pooled, const float* __restrict__ Wfin,
        const float* __restrict__ bfin, float* __restrict__ hfin) {
    __shared__ float s[DCAT];
    int g = blockIdx.x;
    int j = threadIdx.x;
    s[j] = pooled[g * DCAT + j];
    __syncthreads();
    float acc0 = 0.f, acc1 = 0.f, acc2 = 0.f, acc3 = 0.f;
#pragma unroll 4
    for (int k = 0; k < DCAT; k += 4) {
        acc0 += s[k + 0] * __ldg(&Wfin[(k + 0) * DCAT + j]);
        acc1 += s[k + 1] * __ldg(&Wfin[(k + 1) * DCAT + j]);
        acc2 += s[k + 2] * __ldg(&Wfin[(k + 2) * DCAT + j]);
        acc3 += s[k + 3] * __ldg(&Wfin[(k + 3) * DCAT + j]);
    }
    float acc = (acc0 + acc1) + (acc2 + acc3) + __ldg(&bfin[j]);
    hfin[g * DCAT + j] = fmaxf(acc, 0.f);
}

// logits + log_softmax: one warp per graph.
__global__ void __launch_bounds__(32) fin2_kernel(
        const float* __restrict__ hfin, const float* __restrict__ Wout,
        const float* __restrict__ bout, float* __restrict__ out, int out_size) {
    int g = blockIdx.x;
    int lane = threadIdx.x;
    bool valid = lane < NCLS;
    float acc = valid ? __ldg(&bout[lane]) : 0.f;
    for (int k = 0; k < DCAT; k++) {
        float v = __ldg(&hfin[g * DCAT + k]);
        if (valid) acc += v * __ldg(&Wout[k * NCLS + lane]);
    }
    float logit = acc;
    float m = valid ? logit : -INFINITY;
#pragma unroll
    for (int off = 16; off > 0; off >>= 1)
        m = fmaxf(m, __shfl_xor_sync(0xFFFFFFFFu, m, off));
    float e = valid ? expf(logit - m) : 0.f;
#pragma unroll
    for (int off = 16; off > 0; off >>= 1)
        e += __shfl_xor_sync(0xFFFFFFFFu, e, off);
    float ls = logit - m - logf(e);
    if (valid) {
        out[g * NCLS + lane] = logit;
        if (out_size >= 2 * N_GRAPHS * NCLS)
            out[N_GRAPHS * NCLS + g * NCLS + lane] = ls;
    }
}

extern "C" void kernel_launch(void* const* d_in, const int* in_sizes, int n_in,
                              void* d_out, int out_size) {
    const float* x        = (const float*)d_in[0];
    const int*   ei       = (const int*)d_in[1];
    const int*   batch    = (const int*)d_in[2];

    int w = 3;
    if (n_in >= 4 && in_sizes[3] == 1) w = 4;

    const float* W1   = (const float*)d_in[w + 0];
    const float* b1   = (const float*)d_in[w + 1];
    const float* gamma= (const float*)d_in[w + 2];
    const float* beta = (const float*)d_in[w + 3];
    const float* rmean= (const float*)d_in[w + 4];
    const float* rvar = (const float*)d_in[w + 5];
    const float* W2   = (const float*)d_in[w + 6];
    const float* b2   = (const float*)d_in[w + 7];
    const float* Wfin = (const float*)d_in[w + 8];
    const float* bfin = (const float*)d_in[w + 9];
    const float* Wout = (const float*)d_in[w + 10];
    const float* bout = (const float*)d_in[w + 11];
    float* out = (float*)d_out;

    float *pooled, *hfin;
    __half *hh0, *hh1;
    uint2 *wfh, *wfl;
    int *counts, *rowstart, *cursor, *colbuf, *bsum;
    cudaGetSymbolAddress((void**)&hh0,      g_hh0);
    cudaGetSymbolAddress((void**)&hh1,      g_hh1);
    cudaGetSymbolAddress((void**)&pooled,   g_pooled);
    cudaGetSymbolAddress((void**)&hfin,     g_hfin);
    cudaGetSymbolAddress((void**)&counts,   g_counts);
    cudaGetSymbolAddress((void**)&rowstart, g_rowstart);
    cudaGetSymbolAddress((void**)&cursor,   g_cursor);
    cudaGetSymbolAddress((void**)&colbuf,   g_col);
    cudaGetSymbolAddress((void**)&bsum,     g_bsum);
    cudaGetSymbolAddress((void**)&wfh,      g_wfh);
    cudaGetSymbolAddress((void**)&wfl,      g_wfl);

    const int E4B = (N_EDGES / 4 + 255) / 256;
    const int LB = 296;   // 148 SMs x occupancy 2
    int initB = (N_GRAPHS * DCAT + 255) / 256;
    if ((N_NODES + 4 + 255) / 256 > initB) initB = (N_NODES + 4 + 255) / 256;

    init_kernel<<<initB, 256>>>(counts, pooled,
                                hh0 + (long long)N_NODES * DIM,
                                hh1 + (long long)N_NODES * DIM);
    x2h_kernel<<<(N_NODES * DIM / 4 + 255) / 256, 256>>>(
        (const float4*)x, (uint2*)hh0);
    hist_kernel<<<E4B, 256>>>(ei, counts);
    scan1_kernel<<<SCAN_NB, 1024>>>(counts, rowstart, bsum);
    scan2_kernel<<<1, 32>>>(bsum);
    scan3_kernel<<<SCAN_NB, 1024>>>(bsum, counts, rowstart, cursor, colbuf);
    fill_kernel<<<E4B, 256>>>(ei, cursor, colbuf);
    wfrag_kernel<<<(6 * WFRAG_PER_L2 + 255) / 256, 256>>>(W1, W2, wfh, wfl);

    const __half* hin = hh0;
    __half* hout = hh1;
    for (int i = 0; i < NLAYERS; i++) {
        int l2a = i * 2, l2b = i * 2 + 1;
        layer_kernel<<<LB, 256>>>(
            hin, hout,
            wfh + l2a * WFRAG_PER_L2, wfl + l2a * WFRAG_PER_L2,
            wfh + l2b * WFRAG_PER_L2, wfl + l2b * WFRAG_PER_L2,
            b1 + i * DIM,
            gamma + i * DIM, beta + i * DIM, rmean + i * DIM, rvar + i * DIM,
            b2 + i * DIM,
            batch, pooled, i * DIM, rowstart, colbuf);
        const __half* t = hin;
        hin = hout;
        hout = (__half*)t;
    }

    fin1_kernel<<<N_GRAPHS, DCAT>>>(pooled, Wfin, bfin, hfin);
    fin2_kernel<<<N_GRAPHS, 32>>>(hfin, Wout, bout, out, out_size);
}